// round 10
// baseline (speedup 1.0000x reference)
#include <cuda_runtime.h>
#include <math.h>

#define NB      32
#define T_IN    512
#define NEW_T   426
#define NCC     1629            // N*C = 543*3
#define JF      53              // JITTER_FREQ
#define X_ELEMS (NB*NEW_T*NCC)  // 22,205,088
#define BTHREADS 448            // 14 warps: covers scan (426) and 448*4=1792 >= 1629
#define RROWS   6               // 426 = 71 * 6

__device__ __forceinline__ int read_bool(const void* p, int mode, int i) {
    if (mode == 0) return ((const unsigned char*)p)[i] != 0;
    if (mode == 1) return ((const int*)p)[i] != 0;
    return ((const float*)p)[i] != 0.0f;
}

__device__ __forceinline__ int probe_mode(const void* p, int known_true_idx) {
    if (((const unsigned char*)p)[known_true_idx] != 0) return 0;   // u8
    if (((const int*)p)[known_true_idx] == 1) return 1;             // i32
    return 2;                                                       // f32
}

__device__ __forceinline__ void ridx(int tt, int& i0, float& f) {
    float s = (float)tt * (float)(511.0 / 425.0);
    int i = (int)s;
    if (i > T_IN - 2) i = T_IN - 2;
    i0 = i;
    f = s - (float)i;
}

// Row metadata: arm0 (pipelined) + optional arm1 (loaded at consumption; rare).
struct RowMeta {
    const float* p0; float f0, w0;
    const float* p1; float f1, w1;
    bool two;
    float jit;
};

__device__ __forceinline__ RowMeta mkmeta(const float4& tb, int tt,
                                          const float* __restrict__ xb, bool zero_jit)
{
    RowMeta m;
    int i0; float f;
    if (tb.x < 0.0f) {
        ridx(tt, i0, f);
        m.p0 = xb + (size_t)i0 * NCC; m.f0 = f; m.w0 = 1.0f;
        m.two = false; m.p1 = m.p0; m.f1 = 0.f; m.w1 = 0.f;
    } else {
        ridx((int)tb.x, i0, f);
        m.p0 = xb + (size_t)i0 * NCC; m.f0 = f; m.w0 = 1.0f - tb.z;
        int i1; float f1; ridx((int)tb.y, i1, f1);
        m.p1 = xb + (size_t)i1 * NCC; m.f1 = f1; m.w1 = tb.z;
        m.two = true;
    }
    m.jit = zero_jit ? 0.0f : tb.w;
    return m;
}

__device__ __forceinline__ void issue_arm0(const RowMeta& m, const int* nc, const bool* valid,
                                           float* v0, float* v1)
{
    #pragma unroll
    for (int k = 0; k < 4; k++) if (valid[k]) v0[k] = __ldg(m.p0 + nc[k]);
    #pragma unroll
    for (int k = 0; k < 4; k++) if (valid[k]) v1[k] = __ldg(m.p0 + NCC + nc[k]);
}

__device__ __forceinline__ void combine(const RowMeta& m, const int* nc, const bool* valid,
                                        const float* v0, const float* v1, float* cur)
{
    #pragma unroll
    for (int k = 0; k < 4; k++)
        cur[k] = m.w0 * (v0[k] * (1.0f - m.f0) + v1[k] * m.f0);
    if (m.two) {
        float u0[4], u1[4];
        #pragma unroll
        for (int k = 0; k < 4; k++) if (valid[k]) u0[k] = __ldg(m.p1 + nc[k]);
        #pragma unroll
        for (int k = 0; k < 4; k++) if (valid[k]) u1[k] = __ldg(m.p1 + NCC + nc[k]);
        #pragma unroll
        for (int k = 0; k < 4; k++)
            cur[k] += m.w1 * (u0[k] * (1.0f - m.f1) + u1[k] * m.f1);
    }
}

// Fully fused: per-block prologue recomputes the keep-scan + builds the 7 table
// entries it needs in smem; block t0==0 also writes the mask output row.
__global__ void __launch_bounds__(BTHREADS, 3)
main_kernel(const float* __restrict__ x, const float* __restrict__ noise,
            const float* __restrict__ sp, const void* __restrict__ mask,
            const void* __restrict__ keep, const float* __restrict__ bj,
            float* __restrict__ out, int write_mask)
{
    __shared__ int    s_wsum[16];
    __shared__ short  s_kept[NEW_T];
    __shared__ float4 s_tab[RROWS + 1];     // rows t0-1 .. t0+5

    const int t0 = blockIdx.x * RROWS;
    const int b  = blockIdx.y;
    const int row0 = b * NEW_T + t0;
    const int tid = threadIdx.x;
    const int lane = tid & 31, warp = tid >> 5;

    // ---- prologue: keep-bit scan for batch row b ----
    const int bmode = probe_mode(keep, NEW_T - 1);
    const int kv = (tid < NEW_T) ? read_bool(keep, bmode, b * NEW_T + tid) : 0;

    int v = kv;
    #pragma unroll
    for (int off = 1; off < 32; off <<= 1) {
        int n = __shfl_up_sync(0xffffffffu, v, off);
        if (lane >= off) v += n;
    }
    if (lane == 31) s_wsum[warp] = v;
    __syncthreads();
    if (warp == 0 && lane < 14) {
        int w = s_wsum[lane];
        #pragma unroll
        for (int off = 1; off < 14; off <<= 1) {
            int n = __shfl_up_sync(0x3fffu, w, off);
            if (lane >= off) w += n;
        }
        s_wsum[lane] = w;
    }
    __syncthreads();
    const int K = s_wsum[13];               // total kept (threads 426..447 contribute 0)
    const int incl = v + (warp > 0 ? s_wsum[warp - 1] : 0);
    if (tid < NEW_T && kv) s_kept[incl - 1] = (short)tid;
    __syncthreads();

    // ---- build the 7 table entries this block needs ----
    if (tid <= RROWS) {
        const int tt = t0 - 1 + tid;
        if (tt >= 0 && tt < NEW_T) {
            const int kvt = read_bool(keep, bmode, b * NEW_T + tt);
            float s  = (float)tt * (float)(K - 1) / 425.0f;
            int  r0  = (int)floorf(s);
            if (r0 < 0) r0 = 0;
            if (r0 > K - 2) r0 = K - 2;
            float fr = s - (float)r0;

            float4 tb;
            if (kvt) { tb.x = -1.0f; tb.y = 0.0f; tb.z = 0.0f; }
            else     { tb.x = (float)s_kept[r0]; tb.y = (float)s_kept[r0 + 1]; tb.z = fr; }

            float sj = (float)tt * (float)(52.0 / 425.0);
            int  j0  = (int)floorf(sj);
            if (j0 > JF - 2) j0 = JF - 2;
            float fj = sj - (float)j0;
            tb.w = (bj[b * JF + j0] * 0.02f) * (1.0f - fj) + (bj[b * JF + j0 + 1] * 0.02f) * fj;
            s_tab[tid] = tb;
        }
    }

    // ---- mask output (only the t0==0 block of each b) ----
    if (write_mask && t0 == 0 && tid < NEW_T) {
        float nf = (float)tid * (float)(512.0 / 426.0);
        int ni = (int)floorf(nf);
        if (ni > T_IN - 1) ni = T_IN - 1;
        int m = read_bool(mask, bmode, b * T_IN + ni);
        out[X_ELEMS + b * NEW_T + tid] = (m && kv) ? 1.0f : 0.0f;
    }
    __syncthreads();

    // ---- main strip ----
    const float* __restrict__ xb = x + (size_t)b * T_IN * NCC;

    bool valid[4];
    int  nc[4];
    #pragma unroll
    for (int k = 0; k < 4; k++) {
        nc[k] = tid + k * BTHREADS;
        valid[k] = (nc[k] < NCC);
    }

    const size_t sbase = (size_t)b * NCC;
    float spv[4];
    #pragma unroll
    for (int k = 0; k < 4; k++) if (valid[k]) spv[k] = __ldg(sp + sbase + nc[k]);

    // prev = x2(t0-1), unpipelined (once per block)
    float prev[4] = {0.f, 0.f, 0.f, 0.f};
    if (t0 > 0) {
        RowMeta mp = mkmeta(s_tab[0], t0 - 1, xb, false);
        float pv0[4], pv1[4];
        issue_arm0(mp, nc, valid, pv0, pv1);
        combine(mp, nc, valid, pv0, pv1, prev);
    }

    // pipeline prologue: row 0 loads in flight
    RowMeta mc = mkmeta(s_tab[1], t0, xb, t0 == 0);
    float va0[4], va1[4], nz[4];
    issue_arm0(mc, nc, valid, va0, va1);
    {
        const size_t rb = (size_t)row0 * NCC;
        #pragma unroll
        for (int k = 0; k < 4; k++) if (valid[k]) nz[k] = __ldg(noise + rb + nc[k]);
    }

    #pragma unroll
    for (int i = 0; i < RROWS; i++) {
        const int row = row0 + i;

        RowMeta mn;
        float vb0[4], vb1[4], nz2[4];
        if (i + 1 < RROWS) {
            mn = mkmeta(s_tab[i + 2], t0 + i + 1, xb, false);
            issue_arm0(mn, nc, valid, vb0, vb1);
            const size_t rb = (size_t)(row + 1) * NCC;
            #pragma unroll
            for (int k = 0; k < 4; k++) if (valid[k]) nz2[k] = __ldg(noise + rb + nc[k]);
        }

        float cur[4];
        combine(mc, nc, valid, va0, va1, cur);

        const size_t rbase = (size_t)row * NCC;
        const float jit = mc.jit;
        #pragma unroll
        for (int k = 0; k < 4; k++) {
            if (valid[k]) {
                float vv = cur[k] + (cur[k] - prev[k]) * jit;   // jit==0 at t==0
                out[rbase + nc[k]] = vv + nz[k] * 0.01f + spv[k] * 0.005f;
            }
        }

        #pragma unroll
        for (int k = 0; k < 4; k++) { prev[k] = cur[k]; va0[k] = vb0[k]; va1[k] = vb1[k]; nz[k] = nz2[k]; }
        mc = mn;
    }
}

extern "C" void kernel_launch(void* const* d_in, const int* in_sizes, int n_in,
                              void* d_out, int out_size)
{
    const float* x = nullptr; const void* mask = nullptr; const void* keep = nullptr;
    const float* bj = nullptr; const float* noise = nullptr; const float* sp = nullptr;

    for (int i = 0; i < n_in; i++) {
        switch (in_sizes[i]) {
            case NB * T_IN * NCC:  x     = (const float*)d_in[i]; break;
            case NB * T_IN:        mask  = d_in[i];               break;
            case NB * NEW_T:       keep  = d_in[i];               break;
            case NB * JF:          bj    = (const float*)d_in[i]; break;
            case NB * NEW_T * NCC: noise = (const float*)d_in[i]; break;
            case NB * NCC:         sp    = (const float*)d_in[i]; break;
            default: break;
        }
    }

    int write_mask = (out_size >= X_ELEMS + NB * NEW_T) ? 1 : 0;
    dim3 grid(NEW_T / RROWS, NB);   // 71 x 32
    main_kernel<<<grid, BTHREADS>>>(x, noise, sp, mask, keep, bj,
                                    (float*)d_out, write_mask);
}

// round 11
// speedup vs baseline: 1.3702x; 1.3702x over previous
#include <cuda_runtime.h>
#include <math.h>

#define NB      32
#define T_IN    512
#define NEW_T   426
#define NCC     1629            // N*C = 543*3
#define JF      53              // JITTER_FREQ
#define X_ELEMS (NB*NEW_T*NCC)  // 22,205,088
#define BTHREADS 416            // 416*4 = 1664 >= 1629
#define RROWS   6               // 426 = 71 * 6

// Per-(b,t) table: x = idx0 (or -1.0f if frame kept), y = idx1, z = drop-interp frac, w = jitter
__device__ float4 g_tab[NB * NEW_T];

__device__ __forceinline__ int read_bool(const void* p, int mode, int i) {
    if (mode == 0) return ((const unsigned char*)p)[i] != 0;
    if (mode == 1) return ((const int*)p)[i] != 0;
    return ((const float*)p)[i] != 0.0f;
}

__device__ __forceinline__ int probe_mode(const void* p, int known_true_idx) {
    if (((const unsigned char*)p)[known_true_idx] != 0) return 0;   // u8
    if (((const int*)p)[known_true_idx] == 1) return 1;             // i32
    return 2;                                                       // f32
}

// 512 threads: warp-shuffle inclusive scan of keep bits (2 barriers total).
// Triggers programmatic launch completion as soon as g_tab is written.
__global__ void setup_kernel(const void* __restrict__ mask,
                             const void* __restrict__ keep,
                             const float* __restrict__ bj,
                             float* __restrict__ out, int write_mask)
{
    __shared__ int   s_wsum[16];
    __shared__ short s_kept[NEW_T];
    __shared__ int   s_K;
    int b = blockIdx.x;
    int t = threadIdx.x;
    int lane = t & 31, warp = t >> 5;

    int bmode = probe_mode(keep, NEW_T - 1);

    int kv = (t < NEW_T) ? read_bool(keep, bmode, b * NEW_T + t) : 0;

    int v = kv;
    #pragma unroll
    for (int off = 1; off < 32; off <<= 1) {
        int n = __shfl_up_sync(0xffffffffu, v, off);
        if (lane >= off) v += n;
    }
    if (lane == 31) s_wsum[warp] = v;
    __syncthreads();
    if (warp == 0 && lane < 16) {
        int w = s_wsum[lane];
        #pragma unroll
        for (int off = 1; off < 16; off <<= 1) {
            int n = __shfl_up_sync(0xffffu, w, off);
            if (lane >= off) w += n;
        }
        s_wsum[lane] = w;
        if (lane == 13) s_K = w;
    }
    __syncthreads();
    int incl = v + (warp > 0 ? s_wsum[warp - 1] : 0);
    int K = s_K;
    if (t < NEW_T && kv) s_kept[incl - 1] = (short)t;
    __syncthreads();

    if (t < NEW_T) {
        float s  = (float)t * (float)(K - 1) / 425.0f;
        int  r0  = (int)floorf(s);
        if (r0 < 0) r0 = 0;
        if (r0 > K - 2) r0 = K - 2;
        float fr = s - (float)r0;

        float4 tb;
        if (kv) { tb.x = -1.0f; tb.y = 0.0f; tb.z = 0.0f; }
        else    { tb.x = (float)s_kept[r0]; tb.y = (float)s_kept[r0 + 1]; tb.z = fr; }

        float sj = (float)t * (float)(52.0 / 425.0);
        int  j0  = (int)floorf(sj);
        if (j0 > JF - 2) j0 = JF - 2;
        float fj = sj - (float)j0;
        tb.w = (bj[b * JF + j0] * 0.02f) * (1.0f - fj) + (bj[b * JF + j0 + 1] * 0.02f) * fj;

        g_tab[b * NEW_T + t] = tb;
    }

#if __CUDA_ARCH__ >= 900
    // g_tab complete for this CTA -> allow dependent grid to proceed.
    cudaTriggerProgrammaticLaunchCompletion();
#endif

    if (t < NEW_T && write_mask) {
        float nf = (float)t * (float)(512.0 / 426.0);
        int ni = (int)floorf(nf);
        if (ni > T_IN - 1) ni = T_IN - 1;
        int m = read_bool(mask, bmode, b * T_IN + ni);
        out[X_ELEMS + b * NEW_T + t] = (m && kv) ? 1.0f : 0.0f;
    }
}

__device__ __forceinline__ void ridx(int tt, int& i0, float& f) {
    float s = (float)tt * (float)(511.0 / 425.0);
    int i = (int)s;
    if (i > T_IN - 2) i = T_IN - 2;
    i0 = i;
    f = s - (float)i;
}

// Row metadata: arm0 (pipelined) + optional arm1 (loaded at consumption; rare).
struct RowMeta {
    const float* p0; float f0, w0;
    const float* p1; float f1, w1;
    bool two;
    float jit;
};

__device__ __forceinline__ RowMeta mkmeta(const float4& tb, int tt,
                                          const float* __restrict__ xb, bool zero_jit)
{
    RowMeta m;
    int i0; float f;
    if (tb.x < 0.0f) {
        ridx(tt, i0, f);
        m.p0 = xb + (size_t)i0 * NCC; m.f0 = f; m.w0 = 1.0f;
        m.two = false; m.p1 = m.p0; m.f1 = 0.f; m.w1 = 0.f;
    } else {
        ridx((int)tb.x, i0, f);
        m.p0 = xb + (size_t)i0 * NCC; m.f0 = f; m.w0 = 1.0f - tb.z;
        int i1; float f1; ridx((int)tb.y, i1, f1);
        m.p1 = xb + (size_t)i1 * NCC; m.f1 = f1; m.w1 = tb.z;
        m.two = true;
    }
    m.jit = zero_jit ? 0.0f : tb.w;
    return m;
}

__device__ __forceinline__ void issue_arm0(const RowMeta& m, const int* nc, const bool* valid,
                                           float* v0, float* v1)
{
    #pragma unroll
    for (int k = 0; k < 4; k++) if (valid[k]) v0[k] = __ldg(m.p0 + nc[k]);
    #pragma unroll
    for (int k = 0; k < 4; k++) if (valid[k]) v1[k] = __ldg(m.p0 + NCC + nc[k]);
}

__device__ __forceinline__ void combine(const RowMeta& m, const int* nc, const bool* valid,
                                        const float* v0, const float* v1, float* cur)
{
    #pragma unroll
    for (int k = 0; k < 4; k++)
        cur[k] = m.w0 * (v0[k] * (1.0f - m.f0) + v1[k] * m.f0);
    if (m.two) {
        float u0[4], u1[4];
        #pragma unroll
        for (int k = 0; k < 4; k++) if (valid[k]) u0[k] = __ldg(m.p1 + nc[k]);
        #pragma unroll
        for (int k = 0; k < 4; k++) if (valid[k]) u1[k] = __ldg(m.p1 + NCC + nc[k]);
        #pragma unroll
        for (int k = 0; k < 4; k++)
            cur[k] += m.w1 * (u0[k] * (1.0f - m.f1) + u1[k] * m.f1);
    }
}

// One block per (b, 6-row strip); 1-row-deep software pipeline on x arm0 + noise.
// PDL: issues g_tab-independent loads, then grid-dependency-sync, then tab reads.
__global__ void __launch_bounds__(BTHREADS, 3)
main_kernel(const float* __restrict__ x, const float* __restrict__ noise,
            const float* __restrict__ sp, float* __restrict__ out)
{
    const int t0 = blockIdx.x * RROWS;
    const int b  = blockIdx.y;
    const int row0 = b * NEW_T + t0;
    const int tid = threadIdx.x;

    const float* __restrict__ xb = x + (size_t)b * T_IN * NCC;

    bool valid[4];
    int  nc[4];
    #pragma unroll
    for (int k = 0; k < 4; k++) {
        nc[k] = tid + k * BTHREADS;
        valid[k] = (nc[k] < NCC);
    }

    // --- g_tab-independent loads first (overlap with setup under PDL) ---
    const size_t sbase = (size_t)b * NCC;
    float spv[4];
    #pragma unroll
    for (int k = 0; k < 4; k++) if (valid[k]) spv[k] = __ldg(sp + sbase + nc[k]);

    float nz[4];
    {
        const size_t rb = (size_t)row0 * NCC;
        #pragma unroll
        for (int k = 0; k < 4; k++) if (valid[k]) nz[k] = __ldg(noise + rb + nc[k]);
    }

#if __CUDA_ARCH__ >= 900
    cudaGridDependencySynchronize();   // wait for setup's g_tab writes
#endif

    // prev = x2(t0-1), unpipelined (once per block)
    float prev[4] = {0.f, 0.f, 0.f, 0.f};
    if (t0 > 0) {
        RowMeta mp = mkmeta(g_tab[row0 - 1], t0 - 1, xb, false);
        float pv0[4], pv1[4];
        issue_arm0(mp, nc, valid, pv0, pv1);
        combine(mp, nc, valid, pv0, pv1, prev);
    }

    // pipeline prologue: row 0 x-loads in flight
    RowMeta mc = mkmeta(g_tab[row0], t0, xb, t0 == 0);
    float va0[4], va1[4];
    issue_arm0(mc, nc, valid, va0, va1);

    #pragma unroll
    for (int i = 0; i < RROWS; i++) {
        const int row = row0 + i;

        // stage i+1: issue next row's arm0 + noise loads before consuming row i
        RowMeta mn;
        float vb0[4], vb1[4], nz2[4];
        if (i + 1 < RROWS) {
            mn = mkmeta(g_tab[row + 1], t0 + i + 1, xb, false);
            issue_arm0(mn, nc, valid, vb0, vb1);
            const size_t rb = (size_t)(row + 1) * NCC;
            #pragma unroll
            for (int k = 0; k < 4; k++) if (valid[k]) nz2[k] = __ldg(noise + rb + nc[k]);
        }

        // consume row i
        float cur[4];
        combine(mc, nc, valid, va0, va1, cur);

        const size_t rbase = (size_t)row * NCC;
        const float jit = mc.jit;
        #pragma unroll
        for (int k = 0; k < 4; k++) {
            if (valid[k]) {
                float v = cur[k] + (cur[k] - prev[k]) * jit;   // jit==0 at t==0
                out[rbase + nc[k]] = v + nz[k] * 0.01f + spv[k] * 0.005f;
            }
        }

        #pragma unroll
        for (int k = 0; k < 4; k++) { prev[k] = cur[k]; va0[k] = vb0[k]; va1[k] = vb1[k]; nz[k] = nz2[k]; }
        mc = mn;
    }
}

extern "C" void kernel_launch(void* const* d_in, const int* in_sizes, int n_in,
                              void* d_out, int out_size)
{
    const float* x = nullptr; const void* mask = nullptr; const void* keep = nullptr;
    const float* bj = nullptr; const float* noise = nullptr; const float* sp = nullptr;

    for (int i = 0; i < n_in; i++) {
        switch (in_sizes[i]) {
            case NB * T_IN * NCC:  x     = (const float*)d_in[i]; break;
            case NB * T_IN:        mask  = d_in[i];               break;
            case NB * NEW_T:       keep  = d_in[i];               break;
            case NB * JF:          bj    = (const float*)d_in[i]; break;
            case NB * NEW_T * NCC: noise = (const float*)d_in[i]; break;
            case NB * NCC:         sp    = (const float*)d_in[i]; break;
            default: break;
        }
    }

    int write_mask = (out_size >= X_ELEMS + NB * NEW_T) ? 1 : 0;
    setup_kernel<<<NB, 512>>>(mask, keep, bj, (float*)d_out, write_mask);

    dim3 grid(NEW_T / RROWS, NB);   // 71 x 32
    float* outp = (float*)d_out;

    // PDL launch of main; fall back to a plain launch if unsupported.
    cudaLaunchConfig_t cfg = {};
    cfg.gridDim = grid;
    cfg.blockDim = dim3(BTHREADS, 1, 1);
    cfg.dynamicSmemBytes = 0;
    cfg.stream = 0;
    cudaLaunchAttribute attrs[1];
    attrs[0].id = cudaLaunchAttributeProgrammaticStreamSerialization;
    attrs[0].val.programmaticStreamSerializationAllowed = 1;
    cfg.attrs = attrs;
    cfg.numAttrs = 1;

    cudaError_t err = cudaLaunchKernelEx(&cfg, main_kernel, x, noise, sp, outp);
    if (err != cudaSuccess) {
        (void)cudaGetLastError();   // clear sticky error, launch normally
        main_kernel<<<grid, BTHREADS>>>(x, noise, sp, outp);
    }
}